// round 2
// baseline (speedup 1.0000x reference)
#include <cuda_runtime.h>

#define NN   100000
#define NE   1250000
#define FEATD 64
#define HIDD  10
#define PADD  12          // HID padded to 12 floats (48B rows, 16B-aligned float4s)
#define INV_MOD 0.1f

// Scratch (no cudaMalloc allowed): ~40 MB of device globals.
__device__ float g_A[NN * PADD];     // per-node dst-side projection
__device__ float g_B[NN * PADD];     // per-node src-side projection
__device__ float g_agg[NN * PADD];   // per-node aggregation buffer
__device__ float g_T[NN * FEATD];    // intermediate for final dense stage

__device__ __forceinline__ void fma4(float4& acc, float s, const float4 w) {
    acc.x = fmaf(s, w.x, acc.x);
    acc.y = fmaf(s, w.y, acc.y);
    acc.z = fmaf(s, w.z, acc.z);
    acc.w = fmaf(s, w.w, acc.w);
}

// ---------------------------------------------------------------------------
// Layer-0 node precompute: A = X @ W2_0[0:64], B = X @ W2_0[64:128].
// Also zeroes this node's agg row.
// ---------------------------------------------------------------------------
__global__ void __launch_bounds__(128) pre0(const float* __restrict__ X,
                                            const float* __restrict__ W2) {
    // W2_0 is [128, 10]; stage padded to [128, 12] in smem (pad = 0).
    __shared__ float sW[128 * PADD];
    for (int i = threadIdx.x; i < 128 * PADD; i += blockDim.x) {
        int f = i / PADD, k = i % PADD;
        sW[i] = (k < HIDD) ? W2[f * HIDD + k] : 0.0f;
    }
    __syncthreads();

    int n = blockIdx.x * blockDim.x + threadIdx.x;
    if (n >= NN) return;

    const float4* xr  = (const float4*)(X + (long)n * FEATD);
    const float4* sW4 = (const float4*)sW;

    float4 a[3], b[3];
    #pragma unroll
    for (int c = 0; c < 3; c++) { a[c] = make_float4(0.f,0.f,0.f,0.f); b[c] = make_float4(0.f,0.f,0.f,0.f); }

    #pragma unroll 4
    for (int f4 = 0; f4 < 16; f4++) {
        float4 x = xr[f4];
        float xs[4] = {x.x, x.y, x.z, x.w};
        #pragma unroll
        for (int q = 0; q < 4; q++) {
            int f = f4 * 4 + q;
            #pragma unroll
            for (int c = 0; c < 3; c++) {
                fma4(a[c], xs[q], sW4[f * 3 + c]);
                fma4(b[c], xs[q], sW4[(FEATD + f) * 3 + c]);
            }
        }
    }

    float4* Ar = (float4*)(g_A + (long)n * PADD);
    float4* Br = (float4*)(g_B + (long)n * PADD);
    float4* Gr = (float4*)(g_agg + (long)n * PADD);
    float4 z = make_float4(0.f, 0.f, 0.f, 0.f);
    #pragma unroll
    for (int c = 0; c < 3; c++) { Ar[c] = a[c]; Br[c] = b[c]; Gr[c] = z; }
}

// ---------------------------------------------------------------------------
// Layers 1/2 node precompute: h = relu(agg); A = h @ W2[0:10], B = h @ W2[10:20].
// Reads agg, then zeroes its row for the next edge pass.
// ---------------------------------------------------------------------------
__global__ void __launch_bounds__(128) pre12(const float* __restrict__ W2) {
    __shared__ float sW[20 * PADD];
    for (int i = threadIdx.x; i < 20 * PADD; i += blockDim.x) {
        int r = i / PADD, k = i % PADD;
        sW[i] = (k < HIDD) ? W2[r * HIDD + k] : 0.0f;
    }
    __syncthreads();

    int n = blockIdx.x * blockDim.x + threadIdx.x;
    if (n >= NN) return;

    float4* Gr = (float4*)(g_agg + (long)n * PADD);
    float4 g0 = Gr[0], g1 = Gr[1], g2 = Gr[2];
    float h[HIDD];
    h[0]=fmaxf(g0.x,0.f); h[1]=fmaxf(g0.y,0.f); h[2]=fmaxf(g0.z,0.f); h[3]=fmaxf(g0.w,0.f);
    h[4]=fmaxf(g1.x,0.f); h[5]=fmaxf(g1.y,0.f); h[6]=fmaxf(g1.z,0.f); h[7]=fmaxf(g1.w,0.f);
    h[8]=fmaxf(g2.x,0.f); h[9]=fmaxf(g2.y,0.f);

    const float4* sW4 = (const float4*)sW;
    float4 a[3], b[3];
    #pragma unroll
    for (int c = 0; c < 3; c++) { a[c] = make_float4(0.f,0.f,0.f,0.f); b[c] = make_float4(0.f,0.f,0.f,0.f); }
    #pragma unroll
    for (int k = 0; k < HIDD; k++) {
        #pragma unroll
        for (int c = 0; c < 3; c++) {
            fma4(a[c], h[k], sW4[k * 3 + c]);
            fma4(b[c], h[k], sW4[(HIDD + k) * 3 + c]);
        }
    }

    float4* Ar = (float4*)(g_A + (long)n * PADD);
    float4* Br = (float4*)(g_B + (long)n * PADD);
    float4 z = make_float4(0.f, 0.f, 0.f, 0.f);
    #pragma unroll
    for (int c = 0; c < 3; c++) { Ar[c] = a[c]; Br[c] = b[c]; Gr[c] = z; }
}

// ---------------------------------------------------------------------------
// Edge kernel: t = relu(A[dst] + B[src]); u = relu(t @ W1) / MOD;
// agg[dst] += u via vector red.global.
// ---------------------------------------------------------------------------
__global__ void __launch_bounds__(256) edge_kernel(const int* __restrict__ es,
                                                   const int* __restrict__ ed,
                                                   const float* __restrict__ W1) {
    // W1 is [10,10]; staged padded [10,12] (pad = 0).
    __shared__ float sW[HIDD * PADD];
    for (int i = threadIdx.x; i < HIDD * PADD; i += blockDim.x) {
        int k = i / PADD, j = i % PADD;
        sW[i] = (j < HIDD) ? W1[k * HIDD + j] : 0.0f;
    }
    __syncthreads();

    int e = blockIdx.x * blockDim.x + threadIdx.x;
    if (e >= NE) return;

    int s = es[e];
    int d = ed[e];

    const float4* Ar = (const float4*)(g_A + (long)d * PADD);
    const float4* Br = (const float4*)(g_B + (long)s * PADD);
    float4 a0 = Ar[0], a1 = Ar[1], a2 = Ar[2];
    float4 b0 = Br[0], b1 = Br[1], b2 = Br[2];

    float t[HIDD];
    t[0]=fmaxf(a0.x+b0.x,0.f); t[1]=fmaxf(a0.y+b0.y,0.f); t[2]=fmaxf(a0.z+b0.z,0.f); t[3]=fmaxf(a0.w+b0.w,0.f);
    t[4]=fmaxf(a1.x+b1.x,0.f); t[5]=fmaxf(a1.y+b1.y,0.f); t[6]=fmaxf(a1.z+b1.z,0.f); t[7]=fmaxf(a1.w+b1.w,0.f);
    t[8]=fmaxf(a2.x+b2.x,0.f); t[9]=fmaxf(a2.y+b2.y,0.f);

    const float4* sW4 = (const float4*)sW;
    float4 u0 = make_float4(0.f,0.f,0.f,0.f);
    float4 u1 = make_float4(0.f,0.f,0.f,0.f);
    float4 u2 = make_float4(0.f,0.f,0.f,0.f);
    #pragma unroll
    for (int k = 0; k < HIDD; k++) {
        float tk = t[k];
        fma4(u0, tk, sW4[k * 3 + 0]);
        fma4(u1, tk, sW4[k * 3 + 1]);
        fma4(u2, tk, sW4[k * 3 + 2]);
    }

    // relu then scale by 1/MOD
    u0.x = fmaxf(u0.x,0.f)*INV_MOD; u0.y = fmaxf(u0.y,0.f)*INV_MOD;
    u0.z = fmaxf(u0.z,0.f)*INV_MOD; u0.w = fmaxf(u0.w,0.f)*INV_MOD;
    u1.x = fmaxf(u1.x,0.f)*INV_MOD; u1.y = fmaxf(u1.y,0.f)*INV_MOD;
    u1.z = fmaxf(u1.z,0.f)*INV_MOD; u1.w = fmaxf(u1.w,0.f)*INV_MOD;
    u2.x = fmaxf(u2.x,0.f)*INV_MOD; u2.y = fmaxf(u2.y,0.f)*INV_MOD;

    float* Gr = g_agg + (long)d * PADD;   // 48B row stride -> base 16B-aligned
    asm volatile("red.global.add.v4.f32 [%0], {%1, %2, %3, %4};"
                 :: "l"(Gr), "f"(u0.x), "f"(u0.y), "f"(u0.z), "f"(u0.w) : "memory");
    asm volatile("red.global.add.v4.f32 [%0], {%1, %2, %3, %4};"
                 :: "l"(Gr + 4), "f"(u1.x), "f"(u1.y), "f"(u1.z), "f"(u1.w) : "memory");
    asm volatile("red.global.add.v2.f32 [%0], {%1, %2};"
                 :: "l"(Gr + 8), "f"(u2.x), "f"(u2.y) : "memory");
}

// ---------------------------------------------------------------------------
// Final stage 1: T = relu( relu(agg) @ Wf1 )   ([N,10] @ [10,64])
// ---------------------------------------------------------------------------
__global__ void __launch_bounds__(128) final1(const float* __restrict__ Wf1) {
    __shared__ float sW[HIDD * FEATD];   // 640 floats
    for (int i = threadIdx.x; i < HIDD * FEATD; i += blockDim.x) sW[i] = Wf1[i];
    __syncthreads();

    int n = blockIdx.x * blockDim.x + threadIdx.x;
    if (n >= NN) return;

    const float4* Gr = (const float4*)(g_agg + (long)n * PADD);
    float4 g0 = Gr[0], g1 = Gr[1], g2 = Gr[2];
    float h[HIDD];
    h[0]=fmaxf(g0.x,0.f); h[1]=fmaxf(g0.y,0.f); h[2]=fmaxf(g0.z,0.f); h[3]=fmaxf(g0.w,0.f);
    h[4]=fmaxf(g1.x,0.f); h[5]=fmaxf(g1.y,0.f); h[6]=fmaxf(g1.z,0.f); h[7]=fmaxf(g1.w,0.f);
    h[8]=fmaxf(g2.x,0.f); h[9]=fmaxf(g2.y,0.f);

    const float4* sW4 = (const float4*)sW;
    float4 t[16];
    #pragma unroll
    for (int c = 0; c < 16; c++) t[c] = make_float4(0.f,0.f,0.f,0.f);
    #pragma unroll
    for (int k = 0; k < HIDD; k++) {
        float hk = h[k];
        #pragma unroll
        for (int c = 0; c < 16; c++) fma4(t[c], hk, sW4[k * 16 + c]);
    }

    float4* Tr = (float4*)(g_T + (long)n * FEATD);
    #pragma unroll
    for (int c = 0; c < 16; c++) {
        float4 v = t[c];
        v.x = fmaxf(v.x, 0.f); v.y = fmaxf(v.y, 0.f);
        v.z = fmaxf(v.z, 0.f); v.w = fmaxf(v.w, 0.f);
        Tr[c] = v;
    }
}

// ---------------------------------------------------------------------------
// Final stage 2: out = relu( T @ Wf2 )   ([N,64] @ [64,64])
// ---------------------------------------------------------------------------
__global__ void __launch_bounds__(128) final2(const float* __restrict__ Wf2,
                                              float* __restrict__ out) {
    __shared__ float sW[FEATD * FEATD];  // 16 KB
    for (int i = threadIdx.x; i < FEATD * FEATD; i += blockDim.x) sW[i] = Wf2[i];
    __syncthreads();

    int n = blockIdx.x * blockDim.x + threadIdx.x;
    if (n >= NN) return;

    const float4* xr  = (const float4*)(g_T + (long)n * FEATD);
    const float4* sW4 = (const float4*)sW;

    float4 acc[16];
    #pragma unroll
    for (int c = 0; c < 16; c++) acc[c] = make_float4(0.f,0.f,0.f,0.f);

    for (int g4 = 0; g4 < 16; g4++) {   // not fully unrolled: keep I-footprint sane
        float4 x = xr[g4];
        float xs[4] = {x.x, x.y, x.z, x.w};
        #pragma unroll
        for (int q = 0; q < 4; q++) {
            int g = g4 * 4 + q;
            float xg = xs[q];
            #pragma unroll
            for (int c = 0; c < 16; c++) fma4(acc[c], xg, sW4[g * 16 + c]);
        }
    }

    float4* orow = (float4*)(out + (long)n * FEATD);
    #pragma unroll
    for (int c = 0; c < 16; c++) {
        float4 v = acc[c];
        v.x = fmaxf(v.x, 0.f); v.y = fmaxf(v.y, 0.f);
        v.z = fmaxf(v.z, 0.f); v.w = fmaxf(v.w, 0.f);
        orow[c] = v;
    }
}

// ---------------------------------------------------------------------------
// Inputs (metadata order): X, W2_0, W1_0, W2_1, W1_1, W2_2, W1_2, Wf1, Wf2,
//                          edge_src (int32), edge_dst (int32)
// ---------------------------------------------------------------------------
extern "C" void kernel_launch(void* const* d_in, const int* in_sizes, int n_in,
                              void* d_out, int out_size) {
    const float* X    = (const float*)d_in[0];
    const float* W2_0 = (const float*)d_in[1];
    const float* W1_0 = (const float*)d_in[2];
    const float* W2_1 = (const float*)d_in[3];
    const float* W1_1 = (const float*)d_in[4];
    const float* W2_2 = (const float*)d_in[5];
    const float* W1_2 = (const float*)d_in[6];
    const float* Wf1  = (const float*)d_in[7];
    const float* Wf2  = (const float*)d_in[8];
    const int*   es   = (const int*)d_in[9];
    const int*   ed   = (const int*)d_in[10];
    float* out = (float*)d_out;

    const int nodeBlocks = (NN + 127) / 128;
    const int edgeBlocks = (NE + 255) / 256;

    // Layer 0
    pre0<<<nodeBlocks, 128>>>(X, W2_0);
    edge_kernel<<<edgeBlocks, 256>>>(es, ed, W1_0);
    // Layer 1
    pre12<<<nodeBlocks, 128>>>(W2_1);
    edge_kernel<<<edgeBlocks, 256>>>(es, ed, W1_1);
    // Layer 2
    pre12<<<nodeBlocks, 128>>>(W2_2);
    edge_kernel<<<edgeBlocks, 256>>>(es, ed, W1_2);
    // Final dense head
    final1<<<nodeBlocks, 128>>>(Wf1);
    final2<<<nodeBlocks, 128>>>(Wf2, out);
}

// round 4
// speedup vs baseline: 1.2128x; 1.2128x over previous
#include <cuda_runtime.h>
#include <cuda_fp16.h>

#define NN   100000
#define NE   1250000
#define FEATD 64
#define HIDD  10
#define PADD  12          // fp32 agg rows: 12 floats (48B, 16B-aligned)
#define HROW  16          // fp16 A/B rows: 16 halves (32B = one L2 sector)
#define INV_MOD 0.1f

// Scratch (no cudaMalloc allowed).
__device__ __half g_Ah[NN * HROW];   // per-node dst-side projection (fp16)
__device__ __half g_Bh[NN * HROW];   // per-node src-side projection (fp16)
__device__ float  g_agg[NN * PADD];  // per-node aggregation buffer (fp32)

__device__ __forceinline__ void fma4(float4& acc, float s, const float4 w) {
    acc.x = fmaf(s, w.x, acc.x);
    acc.y = fmaf(s, w.y, acc.y);
    acc.z = fmaf(s, w.z, acc.z);
    acc.w = fmaf(s, w.w, acc.w);
}

// Pack 10 fp32 values (in 3 float4s, lanes 10/11 are pad) into a 32B fp16 row.
__device__ __forceinline__ void store_half_row(__half* row, const float4 v0,
                                               const float4 v1, const float4 v2) {
    __align__(16) __half2 h[8];
    h[0] = __floats2half2_rn(v0.x, v0.y);
    h[1] = __floats2half2_rn(v0.z, v0.w);
    h[2] = __floats2half2_rn(v1.x, v1.y);
    h[3] = __floats2half2_rn(v1.z, v1.w);
    h[4] = __floats2half2_rn(v2.x, v2.y);
    h[5] = __floats2half2_rn(0.f, 0.f);
    h[6] = h[5]; h[7] = h[5];
    uint4* p = (uint4*)row;
    p[0] = *(const uint4*)&h[0];
    p[1] = *(const uint4*)&h[4];
}

// ---------------------------------------------------------------------------
// Layer-0 node precompute: A = X @ W2_0[0:64], B = X @ W2_0[64:128]. Zero agg.
// ---------------------------------------------------------------------------
__global__ void __launch_bounds__(128) pre0(const float* __restrict__ X,
                                            const float* __restrict__ W2) {
    __shared__ float sW[128 * PADD];      // [128,10] padded to [128,12]
    for (int i = threadIdx.x; i < 128 * PADD; i += blockDim.x) {
        int f = i / PADD, k = i % PADD;
        sW[i] = (k < HIDD) ? W2[f * HIDD + k] : 0.0f;
    }
    __syncthreads();

    int n = blockIdx.x * blockDim.x + threadIdx.x;
    if (n >= NN) return;

    const float4* xr  = (const float4*)(X + (long)n * FEATD);
    const float4* sW4 = (const float4*)sW;

    float4 a[3], b[3];
    #pragma unroll
    for (int c = 0; c < 3; c++) { a[c] = make_float4(0.f,0.f,0.f,0.f); b[c] = make_float4(0.f,0.f,0.f,0.f); }

    #pragma unroll 4
    for (int f4 = 0; f4 < 16; f4++) {
        float4 x = xr[f4];
        float xs[4] = {x.x, x.y, x.z, x.w};
        #pragma unroll
        for (int q = 0; q < 4; q++) {
            int f = f4 * 4 + q;
            #pragma unroll
            for (int c = 0; c < 3; c++) {
                fma4(a[c], xs[q], sW4[f * 3 + c]);
                fma4(b[c], xs[q], sW4[(FEATD + f) * 3 + c]);
            }
        }
    }

    store_half_row(g_Ah + (size_t)n * HROW, a[0], a[1], a[2]);
    store_half_row(g_Bh + (size_t)n * HROW, b[0], b[1], b[2]);
    float4* Gr = (float4*)(g_agg + (long)n * PADD);
    float4 z = make_float4(0.f, 0.f, 0.f, 0.f);
    Gr[0] = z; Gr[1] = z; Gr[2] = z;
}

// ---------------------------------------------------------------------------
// Layers 1/2 node precompute: h = relu(agg); A = h @ W2[0:10], B = h @ W2[10:20].
// Reads agg, then zeroes its row for the next edge pass.
// ---------------------------------------------------------------------------
__global__ void __launch_bounds__(128) pre12(const float* __restrict__ W2) {
    __shared__ float sW[20 * PADD];
    for (int i = threadIdx.x; i < 20 * PADD; i += blockDim.x) {
        int r = i / PADD, k = i % PADD;
        sW[i] = (k < HIDD) ? W2[r * HIDD + k] : 0.0f;
    }
    __syncthreads();

    int n = blockIdx.x * blockDim.x + threadIdx.x;
    if (n >= NN) return;

    float4* Gr = (float4*)(g_agg + (long)n * PADD);
    float4 g0 = Gr[0], g1 = Gr[1], g2 = Gr[2];
    float h[HIDD];
    h[0]=fmaxf(g0.x,0.f); h[1]=fmaxf(g0.y,0.f); h[2]=fmaxf(g0.z,0.f); h[3]=fmaxf(g0.w,0.f);
    h[4]=fmaxf(g1.x,0.f); h[5]=fmaxf(g1.y,0.f); h[6]=fmaxf(g1.z,0.f); h[7]=fmaxf(g1.w,0.f);
    h[8]=fmaxf(g2.x,0.f); h[9]=fmaxf(g2.y,0.f);

    const float4* sW4 = (const float4*)sW;
    float4 a[3], b[3];
    #pragma unroll
    for (int c = 0; c < 3; c++) { a[c] = make_float4(0.f,0.f,0.f,0.f); b[c] = make_float4(0.f,0.f,0.f,0.f); }
    #pragma unroll
    for (int k = 0; k < HIDD; k++) {
        #pragma unroll
        for (int c = 0; c < 3; c++) {
            fma4(a[c], h[k], sW4[k * 3 + c]);
            fma4(b[c], h[k], sW4[(HIDD + k) * 3 + c]);
        }
    }

    store_half_row(g_Ah + (size_t)n * HROW, a[0], a[1], a[2]);
    store_half_row(g_Bh + (size_t)n * HROW, b[0], b[1], b[2]);
    float4 z = make_float4(0.f, 0.f, 0.f, 0.f);
    Gr[0] = z; Gr[1] = z; Gr[2] = z;
}

// ---------------------------------------------------------------------------
// Edge kernel: t = relu(A[dst] + B[src]); u = relu(t @ W1) / MOD;
// agg[dst] += u via vector red.global. A/B rows are 32B fp16 (1 sector each).
// ---------------------------------------------------------------------------
union H8 { uint4 u; __half2 h[4]; };
union H2 { unsigned u; __half2 h; };

__global__ void __launch_bounds__(256) edge_kernel(const int* __restrict__ es,
                                                   const int* __restrict__ ed,
                                                   const float* __restrict__ W1) {
    __shared__ float sW[HIDD * PADD];     // [10,10] padded to [10,12]
    for (int i = threadIdx.x; i < HIDD * PADD; i += blockDim.x) {
        int k = i / PADD, j = i % PADD;
        sW[i] = (j < HIDD) ? W1[k * HIDD + j] : 0.0f;
    }
    __syncthreads();

    int e = blockIdx.x * blockDim.x + threadIdx.x;
    if (e >= NE) return;

    int s = es[e];
    int d = ed[e];

    const __half* rowA = g_Ah + (size_t)d * HROW;
    const __half* rowB = g_Bh + (size_t)s * HROW;

    H8 aL, bL; H2 aH, bH;
    aL.u = *(const uint4*)rowA;
    aH.u = *(const unsigned*)(rowA + 8);
    bL.u = *(const uint4*)rowB;
    bH.u = *(const unsigned*)(rowB + 8);

    float2 fa0 = __half22float2(aL.h[0]), fb0 = __half22float2(bL.h[0]);
    float2 fa1 = __half22float2(aL.h[1]), fb1 = __half22float2(bL.h[1]);
    float2 fa2 = __half22float2(aL.h[2]), fb2 = __half22float2(bL.h[2]);
    float2 fa3 = __half22float2(aL.h[3]), fb3 = __half22float2(bL.h[3]);
    float2 fa4 = __half22float2(aH.h),    fb4 = __half22float2(bH.h);

    float t[HIDD];
    t[0]=fmaxf(fa0.x+fb0.x,0.f); t[1]=fmaxf(fa0.y+fb0.y,0.f);
    t[2]=fmaxf(fa1.x+fb1.x,0.f); t[3]=fmaxf(fa1.y+fb1.y,0.f);
    t[4]=fmaxf(fa2.x+fb2.x,0.f); t[5]=fmaxf(fa2.y+fb2.y,0.f);
    t[6]=fmaxf(fa3.x+fb3.x,0.f); t[7]=fmaxf(fa3.y+fb3.y,0.f);
    t[8]=fmaxf(fa4.x+fb4.x,0.f); t[9]=fmaxf(fa4.y+fb4.y,0.f);

    const float4* sW4 = (const float4*)sW;
    float4 u0 = make_float4(0.f,0.f,0.f,0.f);
    float4 u1 = make_float4(0.f,0.f,0.f,0.f);
    float4 u2 = make_float4(0.f,0.f,0.f,0.f);
    #pragma unroll
    for (int k = 0; k < HIDD; k++) {
        float tk = t[k];
        fma4(u0, tk, sW4[k * 3 + 0]);
        fma4(u1, tk, sW4[k * 3 + 1]);
        fma4(u2, tk, sW4[k * 3 + 2]);
    }

    u0.x = fmaxf(u0.x,0.f)*INV_MOD; u0.y = fmaxf(u0.y,0.f)*INV_MOD;
    u0.z = fmaxf(u0.z,0.f)*INV_MOD; u0.w = fmaxf(u0.w,0.f)*INV_MOD;
    u1.x = fmaxf(u1.x,0.f)*INV_MOD; u1.y = fmaxf(u1.y,0.f)*INV_MOD;
    u1.z = fmaxf(u1.z,0.f)*INV_MOD; u1.w = fmaxf(u1.w,0.f)*INV_MOD;
    u2.x = fmaxf(u2.x,0.f)*INV_MOD; u2.y = fmaxf(u2.y,0.f)*INV_MOD;

    float* Gr = g_agg + (long)d * PADD;   // 48B rows -> base 16B-aligned
    asm volatile("red.global.add.v4.f32 [%0], {%1, %2, %3, %4};"
                 :: "l"(Gr), "f"(u0.x), "f"(u0.y), "f"(u0.z), "f"(u0.w) : "memory");
    asm volatile("red.global.add.v4.f32 [%0], {%1, %2, %3, %4};"
                 :: "l"(Gr + 4), "f"(u1.x), "f"(u1.y), "f"(u1.z), "f"(u1.w) : "memory");
    asm volatile("red.global.add.v2.f32 [%0], {%1, %2};"
                 :: "l"(Gr + 8), "f"(u2.x), "f"(u2.y) : "memory");
}

// ---------------------------------------------------------------------------
// Fused final head: out = relu( relu( relu(agg) @ Wf1 ) @ Wf2 ).
// T (the [1,64] intermediate) lives entirely in registers.
// ---------------------------------------------------------------------------
__global__ void __launch_bounds__(128) final_fused(const float* __restrict__ Wf1,
                                                   const float* __restrict__ Wf2,
                                                   float* __restrict__ out) {
    __shared__ float sW1[HIDD * FEATD];   // 2.5 KB
    __shared__ float sW2[FEATD * FEATD];  // 16 KB
    for (int i = threadIdx.x; i < HIDD * FEATD; i += blockDim.x) sW1[i] = Wf1[i];
    for (int i = threadIdx.x; i < FEATD * FEATD; i += blockDim.x) sW2[i] = Wf2[i];
    __syncthreads();

    int n = blockIdx.x * blockDim.x + threadIdx.x;
    if (n >= NN) return;

    const float4* Gr = (const float4*)(g_agg + (long)n * PADD);
    float4 g0 = Gr[0], g1 = Gr[1], g2 = Gr[2];
    float h[HIDD];
    h[0]=fmaxf(g0.x,0.f); h[1]=fmaxf(g0.y,0.f); h[2]=fmaxf(g0.z,0.f); h[3]=fmaxf(g0.w,0.f);
    h[4]=fmaxf(g1.x,0.f); h[5]=fmaxf(g1.y,0.f); h[6]=fmaxf(g1.z,0.f); h[7]=fmaxf(g1.w,0.f);
    h[8]=fmaxf(g2.x,0.f); h[9]=fmaxf(g2.y,0.f);

    // Stage 1: T = relu(h @ Wf1), 16 float4s in regs.
    const float4* sW1_4 = (const float4*)sW1;
    float4 t[16];
    #pragma unroll
    for (int c = 0; c < 16; c++) t[c] = make_float4(0.f,0.f,0.f,0.f);
    #pragma unroll
    for (int k = 0; k < HIDD; k++) {
        float hk = h[k];
        #pragma unroll
        for (int c = 0; c < 16; c++) fma4(t[c], hk, sW1_4[k * 16 + c]);
    }
    #pragma unroll
    for (int c = 0; c < 16; c++) {
        t[c].x = fmaxf(t[c].x, 0.f); t[c].y = fmaxf(t[c].y, 0.f);
        t[c].z = fmaxf(t[c].z, 0.f); t[c].w = fmaxf(t[c].w, 0.f);
    }

    // Stage 2: out = relu(T @ Wf2).
    const float4* sW2_4 = (const float4*)sW2;
    float4 acc[16];
    #pragma unroll
    for (int c = 0; c < 16; c++) acc[c] = make_float4(0.f,0.f,0.f,0.f);

    for (int g4 = 0; g4 < 16; g4++) {
        float4 x = t[g4];
        float xs[4] = {x.x, x.y, x.z, x.w};
        #pragma unroll
        for (int q = 0; q < 4; q++) {
            int g = g4 * 4 + q;
            float xg = xs[q];
            #pragma unroll
            for (int c = 0; c < 16; c++) fma4(acc[c], xg, sW2_4[g * 16 + c]);
        }
    }

    float4* orow = (float4*)(out + (long)n * FEATD);
    #pragma unroll
    for (int c = 0; c < 16; c++) {
        float4 v = acc[c];
        v.x = fmaxf(v.x, 0.f); v.y = fmaxf(v.y, 0.f);
        v.z = fmaxf(v.z, 0.f); v.w = fmaxf(v.w, 0.f);
        orow[c] = v;
    }
}

// ---------------------------------------------------------------------------
// Inputs (metadata order): X, W2_0, W1_0, W2_1, W1_1, W2_2, W1_2, Wf1, Wf2,
//                          edge_src (int32), edge_dst (int32)
// ---------------------------------------------------------------------------
extern "C" void kernel_launch(void* const* d_in, const int* in_sizes, int n_in,
                              void* d_out, int out_size) {
    const float* X    = (const float*)d_in[0];
    const float* W2_0 = (const float*)d_in[1];
    const float* W1_0 = (const float*)d_in[2];
    const float* W2_1 = (const float*)d_in[3];
    const float* W1_1 = (const float*)d_in[4];
    const float* W2_2 = (const float*)d_in[5];
    const float* W1_2 = (const float*)d_in[6];
    const float* Wf1  = (const float*)d_in[7];
    const float* Wf2  = (const float*)d_in[8];
    const int*   es   = (const int*)d_in[9];
    const int*   ed   = (const int*)d_in[10];
    float* out = (float*)d_out;

    const int nodeBlocks = (NN + 127) / 128;
    const int edgeBlocks = (NE + 255) / 256;

    pre0<<<nodeBlocks, 128>>>(X, W2_0);
    edge_kernel<<<edgeBlocks, 256>>>(es, ed, W1_0);
    pre12<<<nodeBlocks, 128>>>(W2_1);
    edge_kernel<<<edgeBlocks, 256>>>(es, ed, W1_1);
    pre12<<<nodeBlocks, 128>>>(W2_2);
    edge_kernel<<<edgeBlocks, 256>>>(es, ed, W1_2);
    final_fused<<<nodeBlocks, 128>>>(Wf1, Wf2, out);
}